// round 5
// baseline (speedup 1.0000x reference)
#include <cuda_runtime.h>
#include <cuda_bf16.h>
#include <cuda_fp16.h>
#include <cstdint>

#define NN 100000
#define EE 800000
#define TT 3
#define D  128
#define TND (TT * NN)
#define NCTA 782           // ceil(NN/128)
#define TILE_BYTES 34816   // 128 * 272

// ---------------- device scratch (no allocs allowed) ----------------
__device__ __half g_xws[(size_t)TT * NN * D];       // 76.8 MB fp16 dis-scaled xw
__device__ uint4  g_wb[TT * 2 * (TILE_BYTES / 16)]; // W hi/lo pre-baked smem images
__device__ int    g_deg[TND];                       // deg incl. self
__device__ float  g_dis[TND];
__device__ int    g_off[TND];
__device__ int    g_cur[TND];
__device__ int    g_part[1024];
__device__ int    g_csr[TT * (EE + NN)];            // byte offsets (src*256), self first

// ---------------- helpers ----------------
__device__ __forceinline__ uint32_t smem_u32(const void* p) {
    uint32_t a;
    asm("{ .reg .u64 t; cvta.to.shared.u64 t, %1; cvt.u32.u64 %0, t; }" : "=r"(a) : "l"(p));
    return a;
}
__device__ __forceinline__ void split2(float a, __nv_bfloat16& h, __nv_bfloat16& l) {
    h = __float2bfloat16(a);
    l = __float2bfloat16(a - __bfloat162float(h));
}
__device__ __forceinline__ uint32_t packbf(__nv_bfloat16 a, __nv_bfloat16 b) {
    __nv_bfloat162 p; p.x = a; p.y = b;
    return *(uint32_t*)&p;
}

#define LDSM4(r0, r1, r2, r3, addr)                                              \
    asm volatile("ldmatrix.sync.aligned.m8n8.x4.shared.b16 {%0,%1,%2,%3}, [%4];" \
                 : "=r"(r0), "=r"(r1), "=r"(r2), "=r"(r3) : "r"(addr))

#define MMA_BF16(d, a0, a1, a2, a3, b0, b1)                                   \
    asm volatile("mma.sync.aligned.m16n8k16.row.col.f32.bf16.bf16.f32 "       \
                 "{%0,%1,%2,%3}, {%4,%5,%6,%7}, {%8,%9}, {%0,%1,%2,%3};"      \
                 : "+f"(d[0]), "+f"(d[1]), "+f"(d[2]), "+f"(d[3])             \
                 : "r"(a0), "r"(a1), "r"(a2), "r"(a3), "r"(b0), "r"(b1))

// ---------------- degree ----------------
__global__ void k_deg_init() {
    int i = blockIdx.x * blockDim.x + threadIdx.x;
    if (i < TND) g_deg[i] = 1;   // self loop
}
__global__ void k_deg_count(const int* __restrict__ edges) {
    int i = blockIdx.x * blockDim.x + threadIdx.x;
    if (i >= TT * EE) return;
    int t = i / EE, e = i - t * EE;
    int dst = edges[(size_t)t * 2 * EE + EE + e];
    atomicAdd(&g_deg[t * NN + dst], 1);
}

// ---------------- scan over deg (incl self) + dis; CSR skeleton ----------------
__global__ void k_scan1() {   // 512/block
    __shared__ int s[512];
    int t = threadIdx.x, i = blockIdx.x * 512 + t;
    int v = (i < TND) ? g_deg[i] : 0;
    if (i < TND) g_dis[i] = rsqrtf((float)v);
    s[t] = v;
    __syncthreads();
#pragma unroll
    for (int off = 1; off < 512; off <<= 1) {
        int add = (t >= off) ? s[t - off] : 0;
        __syncthreads();
        s[t] += add;
        __syncthreads();
    }
    if (i < TND) g_off[i] = s[t] - v;      // exclusive, block-local
    if (t == 511) g_part[blockIdx.x] = s[511];
}
__global__ void k_scan2() {   // 1 block, 1024 threads (586 partials)
    __shared__ int s[1024];
    int t = threadIdx.x;
    int v = (t < 586) ? g_part[t] : 0;
    s[t] = v;
    __syncthreads();
#pragma unroll
    for (int off = 1; off < 1024; off <<= 1) {
        int add = (t >= off) ? s[t - off] : 0;
        __syncthreads();
        s[t] += add;
        __syncthreads();
    }
    if (t < 586) g_part[t] = s[t] - v;     // exclusive
}
__global__ void k_scan3() {
    int i = blockIdx.x * blockDim.x + threadIdx.x;
    if (i >= TND) return;
    int v = g_off[i] + g_part[i >> 9];
    g_off[i] = v;
    g_cur[i] = v + 1;                      // edges start after self entry
    int n = i - (i / NN) * NN;             // node id
    g_csr[v] = n << 8;                     // self entry, pre-multiplied byte offset
}
__global__ void k_csr_fill(const int* __restrict__ edges) {
    int i = blockIdx.x * blockDim.x + threadIdx.x;
    if (i >= TT * EE) return;
    int t = i / EE, e = i - t * EE;
    int src = edges[(size_t)t * 2 * EE + e];
    int dst = edges[(size_t)t * 2 * EE + EE + e];
    int pos = atomicAdd(&g_cur[t * NN + dst], 1);
    g_csr[pos] = src << 8;
}

// ---------------- W prebake: hi/lo bf16 in [n][k] stride-136 smem image ----------------
__global__ void k_split_w(const float* __restrict__ W) {
    int i = blockIdx.x * blockDim.x + threadIdx.x;   // 3*128*32 float4s
    if (i >= TT * 128 * 32) return;
    int t = i / (128 * 32);
    int k = (i >> 5) & 127;
    int c4 = i & 31;
    float4 v = *(const float4*)&W[(size_t)t * D * D + k * D + c4 * 4];
    float vv[4] = {v.x, v.y, v.z, v.w};
    unsigned char* hi = (unsigned char*)g_wb + (size_t)(t * 2 + 0) * TILE_BYTES;
    unsigned char* lo = (unsigned char*)g_wb + (size_t)(t * 2 + 1) * TILE_BYTES;
#pragma unroll
    for (int j = 0; j < 4; j++) {
        int n = c4 * 4 + j;
        __nv_bfloat16 h, l;
        split2(vv[j], h, l);
        *(__nv_bfloat16*)(hi + (size_t)n * 272 + k * 2) = h;
        *(__nv_bfloat16*)(lo + (size_t)n * 272 + k * 2) = l;
    }
}

// ---------------- GEMM: xws[t] = dis_t * (x @ W[t]) ----------------
// smem: A_hi[0,34816) A_lo[34816,69632) B_hi[69632,104448) B_lo[104448,139264) dis[139264,+512)
#define SM_AL 34816u
#define SM_B  69632u
#define SM_DIS 139264u
#define SMEM_BYTES 139776u

__global__ void __launch_bounds__(256, 1) k_gemm(const float* __restrict__ x) {
    extern __shared__ char sm[];
    uint32_t sb = smem_u32(sm);
    const int tid = threadIdx.x, lane = tid & 31, warp = tid >> 5;
    const int row0 = blockIdx.x * 128;
    const int wm = warp & 3, wn = warp >> 2;
    const int qr = lane >> 2, qc = lane & 3;

    // ---- A load + hi/lo split (once, reused for all 3 relations) ----
    for (int i = tid; i < 4096; i += 256) {
        int r = i >> 5, c4 = i & 31;
        int gr = row0 + r;
        float4 v = make_float4(0.f, 0.f, 0.f, 0.f);
        if (gr < NN) v = *(const float4*)&x[(size_t)gr * D + c4 * 4];
        __nv_bfloat16 h0, h1, h2, h3, l0, l1, l2, l3;
        split2(v.x, h0, l0); split2(v.y, h1, l1);
        split2(v.z, h2, l2); split2(v.w, h3, l3);
        uint2 hv = make_uint2(packbf(h0, h1), packbf(h2, h3));
        uint2 lv = make_uint2(packbf(l0, l1), packbf(l2, l3));
        uint32_t o = (uint32_t)r * 272 + c4 * 8;
        *(uint2*)(sm + o)         = hv;
        *(uint2*)(sm + SM_AL + o) = lv;
    }

    const uint32_t aoff = sb + (uint32_t)(wm * 32 + (lane & 15)) * 272 + (lane >> 4) * 16;
    const uint32_t boff = sb + SM_B +
        (uint32_t)(wn * 64 + ((lane >> 3) & 1) * 8 + (lane & 7)) * 272 + (lane >> 4) * 16;

    for (int t = 0; t < TT; t++) {
        __syncthreads();   // A ready (t=0) / prev stage copy-out done
        const uint4* bsrc = g_wb + (size_t)t * 2 * (TILE_BYTES / 16);
        for (int i = tid; i < 2 * (TILE_BYTES / 16); i += 256)
            ((uint4*)(sm + SM_B))[i] = bsrc[i];
        if (tid < 128) {
            int gr = row0 + tid;
            ((float*)(sm + SM_DIS))[tid] = (gr < NN) ? g_dis[t * NN + gr] : 0.f;
        }
        __syncthreads();

        float acc[2][8][4];
#pragma unroll
        for (int mt = 0; mt < 2; mt++)
#pragma unroll
            for (int nt = 0; nt < 8; nt++)
#pragma unroll
                for (int j = 0; j < 4; j++) acc[mt][nt][j] = 0.f;

#pragma unroll
        for (int ks = 0; ks < 8; ks++) {
            uint32_t ah[2][4], al[2][4];
#pragma unroll
            for (int mt = 0; mt < 2; mt++) {
                uint32_t a = aoff + mt * 4352 + ks * 32;
                LDSM4(ah[mt][0], ah[mt][1], ah[mt][2], ah[mt][3], a);
                LDSM4(al[mt][0], al[mt][1], al[mt][2], al[mt][3], a + SM_AL);
            }
#pragma unroll
            for (int j = 0; j < 4; j++) {
                uint32_t ba = boff + j * 4352 + ks * 32;
                uint32_t bh[4], bl[4];
                LDSM4(bh[0], bh[1], bh[2], bh[3], ba);
                LDSM4(bl[0], bl[1], bl[2], bl[3], ba + TILE_BYTES);
#pragma unroll
                for (int mt = 0; mt < 2; mt++) {
                    MMA_BF16(acc[mt][2 * j],     ah[mt][0], ah[mt][1], ah[mt][2], ah[mt][3], bh[0], bh[2]);
                    MMA_BF16(acc[mt][2 * j],     ah[mt][0], ah[mt][1], ah[mt][2], ah[mt][3], bl[0], bl[2]);
                    MMA_BF16(acc[mt][2 * j],     al[mt][0], al[mt][1], al[mt][2], al[mt][3], bh[0], bh[2]);
                    MMA_BF16(acc[mt][2 * j + 1], ah[mt][0], ah[mt][1], ah[mt][2], ah[mt][3], bh[1], bh[3]);
                    MMA_BF16(acc[mt][2 * j + 1], ah[mt][0], ah[mt][1], ah[mt][2], ah[mt][3], bl[1], bl[3]);
                    MMA_BF16(acc[mt][2 * j + 1], al[mt][0], al[mt][1], al[mt][2], al[mt][3], bh[1], bh[3]);
                }
            }
        }

        // ---- epilogue: dis-scale, fp16 stage in B region, coalesced copy out ----
        __syncthreads();
#pragma unroll
        for (int mt = 0; mt < 2; mt++) {
            int r0 = wm * 32 + mt * 16 + qr;
            float s0 = ((float*)(sm + SM_DIS))[r0];
            float s1 = ((float*)(sm + SM_DIS))[r0 + 8];
#pragma unroll
            for (int nt = 0; nt < 8; nt++) {
                int col = wn * 64 + nt * 8 + qc * 2;
                *(__half2*)(sm + SM_B + (uint32_t)r0 * 272 + col * 2) =
                    __float22half2_rn(make_float2(acc[mt][nt][0] * s0, acc[mt][nt][1] * s0));
                *(__half2*)(sm + SM_B + (uint32_t)(r0 + 8) * 272 + col * 2) =
                    __float22half2_rn(make_float2(acc[mt][nt][2] * s1, acc[mt][nt][3] * s1));
            }
        }
        __syncthreads();
        for (int i = tid; i < 2048; i += 256) {
            int r = i >> 4, j = i & 15;
            int gr = row0 + r;
            if (gr < NN)
                *(uint4*)(g_xws + ((size_t)t * NN + gr) * D + j * 8) =
                    *(uint4*)(sm + SM_B + (uint32_t)r * 272 + j * 16);
        }
    }
}

// ---------------- gather: warp per node, half-warp per entry parity ----------------
__global__ void k_gather(const float* __restrict__ b, float* __restrict__ out) {
    int w    = (blockIdx.x * blockDim.x + threadIdx.x) >> 5;
    int lane = threadIdx.x & 31;
    if (w >= NN) return;
    const int half = lane >> 4;
    const int l    = lane & 15;
    const uint32_t lb = (uint32_t)l * 16;   // byte offset within 256B row

    float acc[8];
#pragma unroll
    for (int j = 0; j < 8; j++) acc[j] = 0.f;

#pragma unroll
    for (int t = 0; t < TT; t++) {
        const char* xb = (const char*)(g_xws + (size_t)t * NN * D);
        int base = __ldg(&g_off[t * NN + w]);
        int cnt  = __ldg(&g_deg[t * NN + w]);   // entries incl. self
        float tmp[8];
#pragma unroll
        for (int j = 0; j < 8; j++) tmp[j] = 0.f;

#pragma unroll 4
        for (int i = half; i < cnt; i += 2) {
            uint32_t off = (uint32_t)__ldg(&g_csr[base + i]);
            uint4 v = *(const uint4*)(xb + off + lb);
            __half2* h2 = (__half2*)&v;
            float2 f0 = __half22float2(h2[0]);
            float2 f1 = __half22float2(h2[1]);
            float2 f2 = __half22float2(h2[2]);
            float2 f3 = __half22float2(h2[3]);
            tmp[0] += f0.x; tmp[1] += f0.y; tmp[2] += f1.x; tmp[3] += f1.y;
            tmp[4] += f2.x; tmp[5] += f2.y; tmp[6] += f3.x; tmp[7] += f3.y;
        }
        float dn = __ldg(&g_dis[t * NN + w]);
#pragma unroll
        for (int j = 0; j < 8; j++) acc[j] += dn * tmp[j];
    }

    // combine odd-half into even-half
#pragma unroll
    for (int j = 0; j < 8; j++) acc[j] += __shfl_down_sync(0xffffffffu, acc[j], 16);

    if (half == 0) {
#pragma unroll
        for (int t = 0; t < TT; t++) {
            float4 b0 = *(const float4*)&b[t * D + l * 8];
            float4 b1 = *(const float4*)&b[t * D + l * 8 + 4];
            acc[0] += b0.x; acc[1] += b0.y; acc[2] += b0.z; acc[3] += b0.w;
            acc[4] += b1.x; acc[5] += b1.y; acc[6] += b1.z; acc[7] += b1.w;
        }
        float* o = out + (size_t)w * D + l * 8;
        *(float4*)o       = make_float4(acc[0], acc[1], acc[2], acc[3]);
        *(float4*)(o + 4) = make_float4(acc[4], acc[5], acc[6], acc[7]);
    }
}

// ---------------------------------------------------------------------------
extern "C" void kernel_launch(void* const* d_in, const int* in_sizes, int n_in,
                              void* d_out, int out_size) {
    const float* x     = (const float*)d_in[0];   // [N, 128] f32
    const int*   edges = (const int*)d_in[1];     // [3, 2, E] i32
    const float* W     = (const float*)d_in[2];   // [3, 128, 128] f32
    const float* b     = (const float*)d_in[3];   // [3, 128] f32
    float* out = (float*)d_out;                   // [N, 128] f32

    cudaFuncSetAttribute(k_gemm, cudaFuncAttributeMaxDynamicSharedMemorySize, SMEM_BYTES);

    k_deg_init<<<(TND + 255) / 256, 256>>>();
    k_deg_count<<<(TT * EE + 255) / 256, 256>>>(edges);
    k_scan1<<<(TND + 511) / 512, 512>>>();
    k_scan2<<<1, 1024>>>();
    k_scan3<<<(TND + 255) / 256, 256>>>();
    k_csr_fill<<<(TT * EE + 255) / 256, 256>>>(edges);

    k_split_w<<<(TT * 128 * 32 + 255) / 256, 256>>>(W);
    k_gemm<<<NCTA, 256, SMEM_BYTES>>>(x);

    k_gather<<<(NN + 7) / 8, 256>>>(b, out);
}

// round 6
// speedup vs baseline: 1.5584x; 1.5584x over previous
#include <cuda_runtime.h>
#include <cuda_fp16.h>
#include <cstdint>

#define NN 100000
#define EE 800000
#define TT 3
#define D  128
#define TND (TT * NN)
#define NCTA 782           // ceil(NN/128)
#define TILE_BYTES 34816   // 128 * 272

// ---------------- device scratch (no allocs allowed) ----------------
__device__ __half g_xws[(size_t)TT * NN * D];       // 76.8 MB fp16 dis-scaled xw
__device__ uint4  g_wb[TT * (TILE_BYTES / 16)];     // W fp16 pre-baked smem images
__device__ int    g_deg[TND];                       // deg incl. self
__device__ float  g_dis[TND];
__device__ int    g_off[TND];
__device__ int    g_cur[TND];
__device__ int    g_part[1024];
__device__ int    g_csr[TT * (EE + NN)];            // byte offsets (src*256), self first

// ---------------- helpers ----------------
__device__ __forceinline__ uint32_t smem_u32(const void* p) {
    uint32_t a;
    asm("{ .reg .u64 t; cvta.to.shared.u64 t, %1; cvt.u32.u64 %0, t; }" : "=r"(a) : "l"(p));
    return a;
}

#define LDSM4(r0, r1, r2, r3, addr)                                              \
    asm volatile("ldmatrix.sync.aligned.m8n8.x4.shared.b16 {%0,%1,%2,%3}, [%4];" \
                 : "=r"(r0), "=r"(r1), "=r"(r2), "=r"(r3) : "r"(addr))

#define MMA_F16(d, a0, a1, a2, a3, b0, b1)                                    \
    asm volatile("mma.sync.aligned.m16n8k16.row.col.f32.f16.f16.f32 "         \
                 "{%0,%1,%2,%3}, {%4,%5,%6,%7}, {%8,%9}, {%0,%1,%2,%3};"      \
                 : "+f"(d[0]), "+f"(d[1]), "+f"(d[2]), "+f"(d[3])             \
                 : "r"(a0), "r"(a1), "r"(a2), "r"(a3), "r"(b0), "r"(b1))

// ---------------- init: deg=1 everywhere + W fp16 prebake ----------------
__global__ void k_init(const float* __restrict__ W) {
    int i = blockIdx.x * blockDim.x + threadIdx.x;
    if (i < TND) g_deg[i] = 1;                       // self loop
    if (i < TT * 128 * 32) {                         // W: one float4 per thread
        int t = i / (128 * 32);
        int k = (i >> 5) & 127;
        int c4 = i & 31;
        float4 v = *(const float4*)&W[(size_t)t * D * D + k * D + c4 * 4];
        float vv[4] = {v.x, v.y, v.z, v.w};
        unsigned char* img = (unsigned char*)g_wb + (size_t)t * TILE_BYTES;
#pragma unroll
        for (int j = 0; j < 4; j++) {
            int n = c4 * 4 + j;                      // output col -> B row
            *(__half*)(img + (size_t)n * 272 + k * 2) = __float2half_rn(vv[j]);
        }
    }
}

__global__ void k_deg_count(const int* __restrict__ edges) {
    int i = blockIdx.x * blockDim.x + threadIdx.x;
    if (i >= TT * EE) return;
    int t = i / EE, e = i - t * EE;
    int dst = edges[(size_t)t * 2 * EE + EE + e];
    atomicAdd(&g_deg[t * NN + dst], 1);
}

// ---------------- scan over deg (incl self) + dis; CSR skeleton ----------------
__global__ void k_scan1() {   // 512/block
    __shared__ int s[512];
    int t = threadIdx.x, i = blockIdx.x * 512 + t;
    int v = (i < TND) ? g_deg[i] : 0;
    if (i < TND) g_dis[i] = rsqrtf((float)v);
    s[t] = v;
    __syncthreads();
#pragma unroll
    for (int off = 1; off < 512; off <<= 1) {
        int add = (t >= off) ? s[t - off] : 0;
        __syncthreads();
        s[t] += add;
        __syncthreads();
    }
    if (i < TND) g_off[i] = s[t] - v;      // exclusive, block-local
    if (t == 511) g_part[blockIdx.x] = s[511];
}
__global__ void k_scan2() {   // 1 block, 1024 threads (586 partials)
    __shared__ int s[1024];
    int t = threadIdx.x;
    int v = (t < 586) ? g_part[t] : 0;
    s[t] = v;
    __syncthreads();
#pragma unroll
    for (int off = 1; off < 1024; off <<= 1) {
        int add = (t >= off) ? s[t - off] : 0;
        __syncthreads();
        s[t] += add;
        __syncthreads();
    }
    if (t < 586) g_part[t] = s[t] - v;     // exclusive
}
__global__ void k_scan3() {
    int i = blockIdx.x * blockDim.x + threadIdx.x;
    if (i >= TND) return;
    int v = g_off[i] + g_part[i >> 9];
    g_off[i] = v;
    g_cur[i] = v + 1;                      // edges start after self entry
    int n = i - (i / NN) * NN;             // node id
    g_csr[v] = n << 8;                     // self entry, byte offset (256B rows)
}
__global__ void k_csr_fill(const int* __restrict__ edges) {
    int i = blockIdx.x * blockDim.x + threadIdx.x;
    if (i >= TT * EE) return;
    int t = i / EE, e = i - t * EE;
    int src = edges[(size_t)t * 2 * EE + e];
    int dst = edges[(size_t)t * 2 * EE + EE + e];
    int pos = atomicAdd(&g_cur[t * NN + dst], 1);
    g_csr[pos] = src << 8;
}

// ---------------- GEMM: xws[t] = dis_t * (x @ W[t]), fp16 single-pass ----------------
// smem: A[0,34816) B[34816,69632) dis[69632,+512). B region reused as fp16 out stage.
#define SM_B   34816u
#define SM_DIS 69632u
#define SMEM_BYTES 70144u

__global__ void __launch_bounds__(256, 2) k_gemm(const float* __restrict__ x) {
    extern __shared__ char sm[];
    uint32_t sb = smem_u32(sm);
    const int tid = threadIdx.x, lane = tid & 31, warp = tid >> 5;
    const int row0 = blockIdx.x * 128;
    const int wm = warp & 3, wn = warp >> 2;
    const int qr = lane >> 2, qc = lane & 3;

    // ---- A load: f32 -> fp16, once; reused for all 3 relations ----
    for (int i = tid; i < 4096; i += 256) {
        int r = i >> 5, c4 = i & 31;
        int gr = row0 + r;
        float4 v = make_float4(0.f, 0.f, 0.f, 0.f);
        if (gr < NN) v = *(const float4*)&x[(size_t)gr * D + c4 * 4];
        __half2 h0 = __float22half2_rn(make_float2(v.x, v.y));
        __half2 h1 = __float22half2_rn(make_float2(v.z, v.w));
        *(uint2*)(sm + (uint32_t)r * 272 + c4 * 8) =
            make_uint2(*(uint32_t*)&h0, *(uint32_t*)&h1);
    }

    const uint32_t aoff = sb + (uint32_t)(wm * 32 + (lane & 15)) * 272 + (lane >> 4) * 16;
    const uint32_t boff = sb + SM_B +
        (uint32_t)(wn * 64 + ((lane >> 3) & 1) * 8 + (lane & 7)) * 272 + (lane >> 4) * 16;

    for (int t = 0; t < TT; t++) {
        __syncthreads();   // A ready (t=0) / prev stage copy-out done
        const uint4* bsrc = g_wb + (size_t)t * (TILE_BYTES / 16);
        for (int i = tid; i < TILE_BYTES / 16; i += 256)
            ((uint4*)(sm + SM_B))[i] = bsrc[i];
        if (tid < 128) {
            int gr = row0 + tid;
            ((float*)(sm + SM_DIS))[tid] = (gr < NN) ? g_dis[t * NN + gr] : 0.f;
        }
        __syncthreads();

        float acc[2][8][4];
#pragma unroll
        for (int mt = 0; mt < 2; mt++)
#pragma unroll
            for (int nt = 0; nt < 8; nt++)
#pragma unroll
                for (int j = 0; j < 4; j++) acc[mt][nt][j] = 0.f;

#pragma unroll
        for (int ks = 0; ks < 8; ks++) {
            uint32_t ah[2][4];
#pragma unroll
            for (int mt = 0; mt < 2; mt++) {
                uint32_t a = aoff + mt * 4352 + ks * 32;
                LDSM4(ah[mt][0], ah[mt][1], ah[mt][2], ah[mt][3], a);
            }
#pragma unroll
            for (int j = 0; j < 4; j++) {
                uint32_t ba = boff + j * 4352 + ks * 32;
                uint32_t bh[4];
                LDSM4(bh[0], bh[1], bh[2], bh[3], ba);
#pragma unroll
                for (int mt = 0; mt < 2; mt++) {
                    MMA_F16(acc[mt][2 * j],     ah[mt][0], ah[mt][1], ah[mt][2], ah[mt][3], bh[0], bh[2]);
                    MMA_F16(acc[mt][2 * j + 1], ah[mt][0], ah[mt][1], ah[mt][2], ah[mt][3], bh[1], bh[3]);
                }
            }
        }

        // ---- epilogue: dis-scale, fp16 stage in B region, coalesced copy out ----
        __syncthreads();
#pragma unroll
        for (int mt = 0; mt < 2; mt++) {
            int r0 = wm * 32 + mt * 16 + qr;
            float s0 = ((float*)(sm + SM_DIS))[r0];
            float s1 = ((float*)(sm + SM_DIS))[r0 + 8];
#pragma unroll
            for (int nt = 0; nt < 8; nt++) {
                int col = wn * 64 + nt * 8 + qc * 2;
                *(__half2*)(sm + SM_B + (uint32_t)r0 * 272 + col * 2) =
                    __float22half2_rn(make_float2(acc[mt][nt][0] * s0, acc[mt][nt][1] * s0));
                *(__half2*)(sm + SM_B + (uint32_t)(r0 + 8) * 272 + col * 2) =
                    __float22half2_rn(make_float2(acc[mt][nt][2] * s1, acc[mt][nt][3] * s1));
            }
        }
        __syncthreads();
        for (int i = tid; i < 2048; i += 256) {
            int r = i >> 4, j = i & 15;
            int gr = row0 + r;
            if (gr < NN)
                *(uint4*)(g_xws + ((size_t)t * NN + gr) * D + j * 8) =
                    *(uint4*)(sm + SM_B + (uint32_t)r * 272 + j * 16);
        }
    }
}

// ---------------- gather: one warp per node, full-warp 8B lanes ----------------
__global__ void k_gather(const float* __restrict__ b, float* __restrict__ out) {
    int w    = (blockIdx.x * blockDim.x + threadIdx.x) >> 5;   // node id
    int lane = threadIdx.x & 31;
    if (w >= NN) return;
    const uint32_t lb = (uint32_t)lane * 8;    // byte offset within 256B row (4 halfs)

    // bias sum as accumulator init
    float acc[4];
    {
        float4 b0 = *(const float4*)&b[0 * D + lane * 4];
        float4 b1 = *(const float4*)&b[1 * D + lane * 4];
        float4 b2 = *(const float4*)&b[2 * D + lane * 4];
        acc[0] = b0.x + b1.x + b2.x; acc[1] = b0.y + b1.y + b2.y;
        acc[2] = b0.z + b1.z + b2.z; acc[3] = b0.w + b1.w + b2.w;
    }

#pragma unroll
    for (int t = 0; t < TT; t++) {
        const char* xb = (const char*)(g_xws + (size_t)t * NN * D);
        int base = __ldg(&g_off[t * NN + w]);
        int cnt  = __ldg(&g_deg[t * NN + w]);   // entries incl. self
        float tmp[4] = {0.f, 0.f, 0.f, 0.f};
#pragma unroll 4
        for (int i = 0; i < cnt; i++) {
            uint32_t off = (uint32_t)__ldg(&g_csr[base + i]);
            uint2 v = *(const uint2*)(xb + off + lb);
            __half2* h2 = (__half2*)&v;
            float2 f0 = __half22float2(h2[0]);
            float2 f1 = __half22float2(h2[1]);
            tmp[0] += f0.x; tmp[1] += f0.y; tmp[2] += f1.x; tmp[3] += f1.y;
        }
        float dn = __ldg(&g_dis[t * NN + w]);
        acc[0] += dn * tmp[0]; acc[1] += dn * tmp[1];
        acc[2] += dn * tmp[2]; acc[3] += dn * tmp[3];
    }
    *(float4*)&out[(size_t)w * D + lane * 4] = make_float4(acc[0], acc[1], acc[2], acc[3]);
}

// ---------------------------------------------------------------------------
extern "C" void kernel_launch(void* const* d_in, const int* in_sizes, int n_in,
                              void* d_out, int out_size) {
    const float* x     = (const float*)d_in[0];   // [N, 128] f32
    const int*   edges = (const int*)d_in[1];     // [3, 2, E] i32
    const float* W     = (const float*)d_in[2];   // [3, 128, 128] f32
    const float* b     = (const float*)d_in[3];   // [3, 128] f32
    float* out = (float*)d_out;                   // [N, 128] f32

    cudaFuncSetAttribute(k_gemm, cudaFuncAttributeMaxDynamicSharedMemorySize, SMEM_BYTES);

    k_init<<<(TND + 255) / 256, 256>>>(W);
    k_deg_count<<<(TT * EE + 255) / 256, 256>>>(edges);
    k_scan1<<<(TND + 511) / 512, 512>>>();
    k_scan2<<<1, 1024>>>();
    k_scan3<<<(TND + 255) / 256, 256>>>();
    k_csr_fill<<<(TT * EE + 255) / 256, 256>>>(edges);

    k_gemm<<<NCTA, 256, SMEM_BYTES>>>(x);

    k_gather<<<(NN + 7) / 8, 256>>>(b, out);
}